// round 2
// baseline (speedup 1.0000x reference)
#include <cuda_runtime.h>
#include <cuda_bf16.h>
#include <math.h>

// Problem constants
#define B_   128
#define T_   2048
#define F_   512
#define OS_  20
#define OF_  42
#define NC_  10
#define NCHUNK_ 8
#define CHUNK_  256   // NCHUNK_*CHUNK_ == T_

// -------- device scratch (no allocation allowed) --------
__device__ float g_partial[B_ * NCHUNK_ * F_];   // 2 MB
__device__ float g_x[B_ * F_ * OS_];             // 5.24 MB, layout [b][f][j]
__device__ float g_scale[F_];
__device__ float g_shift[F_];

// ============================================================
// Kernel 1: partial column sums of y over t in [chunk] ∩ [0, fs)
// grid = (NCHUNK_, B_), block = 128 threads, float4 per thread
// ============================================================
__global__ void k_pool_partial(const float* __restrict__ y,
                               const int*   __restrict__ lengths) {
    const int c = blockIdx.x;
    const int b = blockIdx.y;
    const int tid = threadIdx.x;           // covers f = 4*tid .. 4*tid+3

    const int fs = lengths[b] - (OS_ - 1);
    int t0 = c * CHUNK_;
    int t1 = min(t0 + CHUNK_, fs);

    const float4* row = reinterpret_cast<const float4*>(y + (size_t)b * T_ * F_);
    const int rstride = F_ / 4;   // 128 float4 per row

    float4 acc = make_float4(0.f, 0.f, 0.f, 0.f);
    int t = t0;
    for (; t + 8 <= t1; t += 8) {
        float4 v0 = __ldcs(&row[(t + 0) * rstride + tid]);
        float4 v1 = __ldcs(&row[(t + 1) * rstride + tid]);
        float4 v2 = __ldcs(&row[(t + 2) * rstride + tid]);
        float4 v3 = __ldcs(&row[(t + 3) * rstride + tid]);
        float4 v4 = __ldcs(&row[(t + 4) * rstride + tid]);
        float4 v5 = __ldcs(&row[(t + 5) * rstride + tid]);
        float4 v6 = __ldcs(&row[(t + 6) * rstride + tid]);
        float4 v7 = __ldcs(&row[(t + 7) * rstride + tid]);
        acc.x += v0.x; acc.y += v0.y; acc.z += v0.z; acc.w += v0.w;
        acc.x += v1.x; acc.y += v1.y; acc.z += v1.z; acc.w += v1.w;
        acc.x += v2.x; acc.y += v2.y; acc.z += v2.z; acc.w += v2.w;
        acc.x += v3.x; acc.y += v3.y; acc.z += v3.z; acc.w += v3.w;
        acc.x += v4.x; acc.y += v4.y; acc.z += v4.z; acc.w += v4.w;
        acc.x += v5.x; acc.y += v5.y; acc.z += v5.z; acc.w += v5.w;
        acc.x += v6.x; acc.y += v6.y; acc.z += v6.z; acc.w += v6.w;
        acc.x += v7.x; acc.y += v7.y; acc.z += v7.z; acc.w += v7.w;
    }
    for (; t < t1; ++t) {
        float4 v = __ldcs(&row[t * rstride + tid]);
        acc.x += v.x; acc.y += v.y; acc.z += v.z; acc.w += v.w;
    }

    float4* out = reinterpret_cast<float4*>(g_partial + (size_t)(b * NCHUNK_ + c) * F_);
    out[tid] = acc;
}

// ============================================================
// Kernel 2: finish pooling.
// x[b,j,f] = (sum_{t=j}^{fs+j-1} y[b,t,f]) / fs
//          = (base - prefix(head) + prefix(tail)) / fs
// one thread per (b,f). Writes g_x[b][f][0..19].
// ============================================================
__global__ void k_pool_finish(const float* __restrict__ y,
                              const int*   __restrict__ lengths) {
    const int idx = blockIdx.x * blockDim.x + threadIdx.x;
    if (idx >= B_ * F_) return;
    const int b = idx >> 9;       // F_ = 512
    const int f = idx & (F_ - 1);

    const int fs = lengths[b] - (OS_ - 1);
    const float inv = 1.0f / (float)fs;

    float base = 0.f;
#pragma unroll
    for (int c = 0; c < NCHUNK_; ++c)
        base += g_partial[(size_t)(b * NCHUNK_ + c) * F_ + f];

    const float* yb = y + (size_t)b * T_ * F_ + f;
    float* xo = g_x + (size_t)idx * OS_;

    float run = base;
    xo[0] = run * inv;
#pragma unroll
    for (int j = 1; j < OS_; ++j) {
        run += yb[(size_t)(fs + j - 1) * F_] - yb[(size_t)(j - 1) * F_];
        xo[j] = run * inv;
    }
}

// ============================================================
// Kernel 3: BN stats per channel over (B, OS) = 2560 samples.
// grid = F_ blocks, block = 128 threads (one per b).
// Produces fused scale/shift.
// ============================================================
__global__ void k_bnstats(const float* __restrict__ gamma,
                          const float* __restrict__ beta) {
    const int f = blockIdx.x;
    const int b = threadIdx.x;   // 128

    __shared__ float s1[128];
    __shared__ float s2[128];

    const float* xp = g_x + (size_t)(b * F_ + f) * OS_;
    float s = 0.f, ss = 0.f;
#pragma unroll
    for (int j = 0; j < OS_; ++j) {
        float v = xp[j];
        s += v;
        ss = fmaf(v, v, ss);
    }
    s1[b] = s; s2[b] = ss;
    __syncthreads();
    for (int off = 64; off > 0; off >>= 1) {
        if (b < off) { s1[b] += s1[b + off]; s2[b] += s2[b + off]; }
        __syncthreads();
    }
    if (b == 0) {
        const float n = (float)(B_ * OS_);
        float mu = s1[0] / n;
        float var = s2[0] / n - mu * mu;
        float sc = gamma[f] * rsqrtf(var + 1e-5f);
        g_scale[f] = sc;
        g_shift[f] = beta[f] - mu * sc;
    }
}

// ============================================================
// Kernel 4: per-batch dense net + linear + softmax.
// grid = B_, block = 640 (20 warps; warp = column j, lane = row)
// dynamic smem: xn[512*20] | dbuf[210*20] | wbuf[7098] | logits[16]
// ============================================================
#define NET_THREADS 640
#define SM_XN   0
#define SM_D    (F_ * OS_)                 // 10240
#define SM_W    (SM_D + 210 * OS_)         // 10240 + 4200
#define SM_LG   (SM_W + 42 * 169)          // + 7098
#define SM_FLOATS (SM_LG + 16)

__device__ __forceinline__ void dense_layer(const float* __restrict__ Wg,
                                            const float* __restrict__ bg,
                                            float* wbuf, float* dbuf,
                                            int IN, int OB,
                                            int lane, int j, int tid) {
    const int st = IN + 1;                 // odd stride -> conflict-free
    const int cnt = OF_ * IN;
    for (int idx = tid; idx < cnt; idx += NET_THREADS) {
        int o = idx / IN;
        int i = idx - o * IN;
        wbuf[o * st + i] = Wg[idx];
    }
    __syncthreads();

    float a0 = 0.f, a1 = 0.f;
    for (int i = 0; i < IN; ++i) {
        float v = dbuf[i * OS_ + j];       // broadcast within warp
        a0 = fmaf(wbuf[lane * st + i], v, a0);
        if (lane < 10) a1 = fmaf(wbuf[(lane + 32) * st + i], v, a1);
    }
    __syncthreads();
    dbuf[(OB + lane) * OS_ + j] = fmaxf(a0 + bg[lane], 0.f);
    if (lane < 10)
        dbuf[(OB + lane + 32) * OS_ + j] = fmaxf(a1 + bg[lane + 32], 0.f);
    __syncthreads();
}

__global__ void __launch_bounds__(NET_THREADS, 1)
k_net(const float* __restrict__ W1, const float* __restrict__ b1,
      const float* __restrict__ W2, const float* __restrict__ b2,
      const float* __restrict__ W3, const float* __restrict__ b3,
      const float* __restrict__ W4, const float* __restrict__ b4,
      const float* __restrict__ W5, const float* __restrict__ b5,
      const float* __restrict__ Wlin, const float* __restrict__ blin,
      float* __restrict__ out) {
    extern __shared__ float sm[];
    float* xn   = sm + SM_XN;
    float* dbuf = sm + SM_D;
    float* wbuf = sm + SM_W;
    float* lg   = sm + SM_LG;

    const int tid  = threadIdx.x;
    const int lane = tid & 31;
    const int j    = tid >> 5;            // 0..19
    const int b    = blockIdx.x;

    // load + BN-normalize x into smem (coalesced)
    const float* xg = g_x + (size_t)b * F_ * OS_;
    for (int idx = tid; idx < F_ * OS_; idx += NET_THREADS) {
        int f = idx / OS_;
        xn[idx] = fmaf(xg[idx], g_scale[f], g_shift[f]);
    }
    __syncthreads();

    // ---- layer 1: c1 = relu(W1[42,512] @ xn + b1), 8 tiles of 64 f ----
    {
        float a0 = 0.f, a1 = 0.f;
        for (int ft = 0; ft < 8; ++ft) {
            for (int idx = tid; idx < OF_ * 64; idx += NET_THREADS) {
                int o = idx >> 6, fi = idx & 63;
                wbuf[o * 65 + fi] = W1[o * F_ + (ft << 6) + fi];
            }
            __syncthreads();
#pragma unroll
            for (int fi = 0; fi < 64; ++fi) {
                float v = xn[((ft << 6) + fi) * OS_ + j];
                a0 = fmaf(wbuf[lane * 65 + fi], v, a0);
                if (lane < 10) a1 = fmaf(wbuf[(lane + 32) * 65 + fi], v, a1);
            }
            __syncthreads();
        }
        dbuf[lane * OS_ + j] = fmaxf(a0 + b1[lane], 0.f);
        if (lane < 10)
            dbuf[(lane + 32) * OS_ + j] = fmaxf(a1 + b1[lane + 32], 0.f);
        __syncthreads();
    }

    // ---- layers 2..5 (dense concat is implicit: rows accumulate in dbuf) ----
    dense_layer(W2, b2, wbuf, dbuf,  42,  42, lane, j, tid);
    dense_layer(W3, b3, wbuf, dbuf,  84,  84, lane, j, tid);
    dense_layer(W4, b4, wbuf, dbuf, 126, 126, lane, j, tid);
    dense_layer(W5, b5, wbuf, dbuf, 168, 168, lane, j, tid);

    // ---- linear head: logits[n] = Wlin[n,:4200] . dbuf + blin ----
    if (j < NC_) {
        float acc = 0.f;
        for (int idx = lane; idx < 210 * OS_; idx += 32)
            acc = fmaf(Wlin[j * (210 * OS_) + idx], dbuf[idx], acc);
#pragma unroll
        for (int off = 16; off > 0; off >>= 1)
            acc += __shfl_down_sync(0xffffffffu, acc, off);
        if (lane == 0) lg[j] = acc + blin[j];
    }
    __syncthreads();

    // ---- softmax over 10 ----
    if (tid == 0) {
        float m = lg[0];
#pragma unroll
        for (int n = 1; n < NC_; ++n) m = fmaxf(m, lg[n]);
        float e[NC_], s = 0.f;
#pragma unroll
        for (int n = 0; n < NC_; ++n) { e[n] = __expf(lg[n] - m); s += e[n]; }
        float invs = 1.f / s;
#pragma unroll
        for (int n = 0; n < NC_; ++n) out[b * NC_ + n] = e[n] * invs;
    }
}

// ============================================================
extern "C" void kernel_launch(void* const* d_in, const int* in_sizes, int n_in,
                              void* d_out, int out_size) {
    const float* y       = (const float*)d_in[0];
    const int*   lengths = (const int*)  d_in[1];
    const float* gamma   = (const float*)d_in[2];
    const float* beta    = (const float*)d_in[3];
    const float* W1 = (const float*)d_in[4];
    const float* b1 = (const float*)d_in[5];
    const float* W2 = (const float*)d_in[6];
    const float* b2 = (const float*)d_in[7];
    const float* W3 = (const float*)d_in[8];
    const float* b3 = (const float*)d_in[9];
    const float* W4 = (const float*)d_in[10];
    const float* b4 = (const float*)d_in[11];
    const float* W5 = (const float*)d_in[12];
    const float* b5 = (const float*)d_in[13];
    const float* Wlin = (const float*)d_in[14];
    const float* blin = (const float*)d_in[15];
    float* out = (float*)d_out;

    const size_t smem_bytes = SM_FLOATS * sizeof(float);   // ~86 KB
    cudaFuncSetAttribute(k_net, cudaFuncAttributeMaxDynamicSharedMemorySize,
                         (int)smem_bytes);

    dim3 g1(NCHUNK_, B_);
    k_pool_partial<<<g1, 128>>>(y, lengths);
    k_pool_finish<<<(B_ * F_) / 256, 256>>>(y, lengths);
    k_bnstats<<<F_, 128>>>(gamma, beta);
    k_net<<<B_, NET_THREADS, smem_bytes>>>(W1, b1, W2, b2, W3, b3, W4, b4,
                                           W5, b5, Wlin, blin, out);
}

// round 3
// speedup vs baseline: 1.0967x; 1.0967x over previous
#include <cuda_runtime.h>
#include <cuda_bf16.h>
#include <math.h>

// Problem constants
#define B_   128
#define T_   2048
#define F_   512
#define OS_  20
#define OF_  42
#define NC_  10
#define NCHUNK_ 8
#define CHUNK_  256   // NCHUNK_*CHUNK_ == T_

// -------- device scratch (no allocation allowed) --------
__device__ float g_partial[B_ * NCHUNK_ * F_];   // 2 MB
__device__ float g_x[B_ * F_ * OS_];             // [b][f][j]
__device__ float g_act[210 * B_ * OS_];          // c1 rows 0..41, [row][col], col=b*20+j
__device__ float g_scale[F_];
__device__ float g_shift[F_];

// ============================================================
// Kernel 1: partial column sums of y over t in [chunk] ∩ [0, fs)
// ============================================================
__global__ void k_pool_partial(const float* __restrict__ y,
                               const int*   __restrict__ lengths) {
    const int c = blockIdx.x;
    const int b = blockIdx.y;
    const int tid = threadIdx.x;

    const int fs = lengths[b] - (OS_ - 1);
    int t0 = c * CHUNK_;
    int t1 = min(t0 + CHUNK_, fs);

    const float4* row = reinterpret_cast<const float4*>(y + (size_t)b * T_ * F_);
    const int rstride = F_ / 4;

    float4 acc = make_float4(0.f, 0.f, 0.f, 0.f);
    int t = t0;
    for (; t + 8 <= t1; t += 8) {
        float4 v0 = __ldcs(&row[(t + 0) * rstride + tid]);
        float4 v1 = __ldcs(&row[(t + 1) * rstride + tid]);
        float4 v2 = __ldcs(&row[(t + 2) * rstride + tid]);
        float4 v3 = __ldcs(&row[(t + 3) * rstride + tid]);
        float4 v4 = __ldcs(&row[(t + 4) * rstride + tid]);
        float4 v5 = __ldcs(&row[(t + 5) * rstride + tid]);
        float4 v6 = __ldcs(&row[(t + 6) * rstride + tid]);
        float4 v7 = __ldcs(&row[(t + 7) * rstride + tid]);
        acc.x += v0.x; acc.y += v0.y; acc.z += v0.z; acc.w += v0.w;
        acc.x += v1.x; acc.y += v1.y; acc.z += v1.z; acc.w += v1.w;
        acc.x += v2.x; acc.y += v2.y; acc.z += v2.z; acc.w += v2.w;
        acc.x += v3.x; acc.y += v3.y; acc.z += v3.z; acc.w += v3.w;
        acc.x += v4.x; acc.y += v4.y; acc.z += v4.z; acc.w += v4.w;
        acc.x += v5.x; acc.y += v5.y; acc.z += v5.z; acc.w += v5.w;
        acc.x += v6.x; acc.y += v6.y; acc.z += v6.z; acc.w += v6.w;
        acc.x += v7.x; acc.y += v7.y; acc.z += v7.z; acc.w += v7.w;
    }
    for (; t < t1; ++t) {
        float4 v = __ldcs(&row[t * rstride + tid]);
        acc.x += v.x; acc.y += v.y; acc.z += v.z; acc.w += v.w;
    }

    float4* out = reinterpret_cast<float4*>(g_partial + (size_t)(b * NCHUNK_ + c) * F_);
    out[tid] = acc;
}

// ============================================================
// Kernel 2: finish pooling. x[b,j,f] = sliding-window mean.
// one thread per (b,f). Writes g_x[b][f][0..19] (20 contiguous).
// ============================================================
__global__ void k_pool_finish(const float* __restrict__ y,
                              const int*   __restrict__ lengths) {
    const int idx = blockIdx.x * blockDim.x + threadIdx.x;
    if (idx >= B_ * F_) return;
    const int b = idx >> 9;
    const int f = idx & (F_ - 1);

    const int fs = lengths[b] - (OS_ - 1);
    const float inv = 1.0f / (float)fs;

    float base = 0.f;
#pragma unroll
    for (int c = 0; c < NCHUNK_; ++c)
        base += g_partial[(size_t)(b * NCHUNK_ + c) * F_ + f];

    const float* yb = y + (size_t)b * T_ * F_ + f;
    float* xo = g_x + (size_t)idx * OS_;

    float run = base;
    xo[0] = run * inv;
#pragma unroll
    for (int j = 1; j < OS_; ++j) {
        run += yb[(size_t)(fs + j - 1) * F_] - yb[(size_t)(j - 1) * F_];
        xo[j] = run * inv;
    }
}

// ============================================================
// Kernel 3: BN stats per channel -> fused scale/shift.
// ============================================================
__global__ void k_bnstats(const float* __restrict__ gamma,
                          const float* __restrict__ beta) {
    const int f = blockIdx.x;
    const int b = threadIdx.x;

    __shared__ float s1[128];
    __shared__ float s2[128];

    const float* xp = g_x + (size_t)(b * F_ + f) * OS_;
    float s = 0.f, ss = 0.f;
#pragma unroll
    for (int j = 0; j < OS_; ++j) {
        float v = xp[j];
        s += v;
        ss = fmaf(v, v, ss);
    }
    s1[b] = s; s2[b] = ss;
    __syncthreads();
    for (int off = 64; off > 0; off >>= 1) {
        if (b < off) { s1[b] += s1[b + off]; s2[b] += s2[b + off]; }
        __syncthreads();
    }
    if (b == 0) {
        const float n = (float)(B_ * OS_);
        float mu = s1[0] / n;
        float var = s2[0] / n - mu * mu;
        float sc = gamma[f] * rsqrtf(var + 1e-5f);
        g_scale[f] = sc;
        g_shift[f] = beta[f] - mu * sc;
    }
}

// ============================================================
// Kernel 4: layer 1 (K=512). One block per batch, 256 thr.
// 8-way K-split across warps; lane tile = 3 rows x 10 cols.
// smem: a_sT[20][516] | w_s[42][516] | p_s[8][848]
// ============================================================
#define L1_AS 516
#define L1_PS 848
#define L1_SM_A 0
#define L1_SM_W (20 * L1_AS)                 // 10320
#define L1_SM_P (L1_SM_W + 42 * L1_AS)       // 31992
#define L1_SM_FLOATS (L1_SM_P + 8 * L1_PS)   // 38776

__global__ void __launch_bounds__(256, 1)
k_l1(const float* __restrict__ W1, const float* __restrict__ b1) {
    extern __shared__ float sm[];
    float* a_sT = sm + L1_SM_A;   // [c][f] stride 516
    float* w_s  = sm + L1_SM_W;   // [o][i] stride 516
    float* p_s  = sm + L1_SM_P;   // [warp][out] stride 848

    const int tid = threadIdx.x;
    const int b   = blockIdx.x;

    // stage activations (BN-normalized), transposed: a_sT[j][f]
    const float* xg = g_x + (size_t)b * F_ * OS_;
    for (int idx = tid; idx < F_ * OS_; idx += 256) {
        int f = idx / OS_;
        int j = idx - f * OS_;
        a_sT[j * L1_AS + f] = fmaf(xg[idx], g_scale[f], g_shift[f]);
    }
    // stage W1 [42][512] -> stride 516
    for (int idx = tid; idx < OF_ * F_; idx += 256) {
        int o = idx >> 9;
        int i = idx & 511;
        w_s[o * L1_AS + i] = W1[idx];
    }
    __syncthreads();

    const int warp = tid >> 5;
    const int lane = tid & 31;
    const int rg = lane >> 1;     // 0..15 (14,15 idle)
    const int cg = lane & 1;      // col half

    float acc[3][10];
#pragma unroll
    for (int r = 0; r < 3; ++r)
#pragma unroll
        for (int k = 0; k < 10; ++k) acc[r][k] = 0.f;

    if (rg < 14) {
        const int i0 = warp * 64;
        const float* w0p = w_s + (rg)      * L1_AS;
        const float* w1p = w_s + (rg + 14) * L1_AS;
        const float* w2p = w_s + (rg + 28) * L1_AS;
        const float* ap  = a_sT + (cg * 10) * L1_AS;
        for (int i4 = i0; i4 < i0 + 64; i4 += 4) {
            float4 w0 = *reinterpret_cast<const float4*>(w0p + i4);
            float4 w1 = *reinterpret_cast<const float4*>(w1p + i4);
            float4 w2 = *reinterpret_cast<const float4*>(w2p + i4);
#pragma unroll
            for (int k = 0; k < 10; ++k) {
                float4 v = *reinterpret_cast<const float4*>(ap + k * L1_AS + i4);
                acc[0][k] = fmaf(w0.x, v.x, acc[0][k]);
                acc[0][k] = fmaf(w0.y, v.y, acc[0][k]);
                acc[0][k] = fmaf(w0.z, v.z, acc[0][k]);
                acc[0][k] = fmaf(w0.w, v.w, acc[0][k]);
                acc[1][k] = fmaf(w1.x, v.x, acc[1][k]);
                acc[1][k] = fmaf(w1.y, v.y, acc[1][k]);
                acc[1][k] = fmaf(w1.z, v.z, acc[1][k]);
                acc[1][k] = fmaf(w1.w, v.w, acc[1][k]);
                acc[2][k] = fmaf(w2.x, v.x, acc[2][k]);
                acc[2][k] = fmaf(w2.y, v.y, acc[2][k]);
                acc[2][k] = fmaf(w2.z, v.z, acc[2][k]);
                acc[2][k] = fmaf(w2.w, v.w, acc[2][k]);
            }
        }
        float* pp = p_s + warp * L1_PS;
#pragma unroll
        for (int r = 0; r < 3; ++r)
#pragma unroll
            for (int k = 0; k < 10; ++k)
                pp[(rg + 14 * r) * OS_ + (cg * 10 + k)] = acc[r][k];
    }
    __syncthreads();

    // reduce K-split partials, bias+relu, write g_act rows 0..41
    for (int out = tid; out < OF_ * OS_; out += 256) {
        float s = 0.f;
#pragma unroll
        for (int w = 0; w < 8; ++w) s += p_s[w * L1_PS + out];
        int r = out / OS_;
        int c = out - r * OS_;
        g_act[(size_t)r * (B_ * OS_) + b * OS_ + c] = fmaxf(s + b1[r], 0.f);
    }
}

// ============================================================
// Kernel 5: layers 2..5 + linear head + softmax.
// One block per batch, 160 thr (5 warps x 4 cols).
// Activations transposed dbuf_T[pos 20][chan stride 212].
// ============================================================
#define RS_DS 212
#define RS_WS 172
#define RS_SM_D 0
#define RS_SM_W (20 * RS_DS)                 // 4240
#define RS_SM_L (RS_SM_W + 42 * RS_WS)       // 4240 + 7224 = 11464
#define RS_SM_FLOATS (RS_SM_L + 16)

__device__ __forceinline__ void rest_layer(const float* __restrict__ Wg,
                                           const float* __restrict__ bg,
                                           float* db, float* ws,
                                           int IN, int OB,
                                           int warp, int lane, int tid) {
    // stage weights [42][IN] -> stride 172
    const int cnt = OF_ * IN;
    for (int idx = tid; idx < cnt; idx += 160) {
        int o = idx / IN;
        int i = idx - o * IN;
        ws[o * RS_WS + i] = Wg[idx];
    }
    __syncthreads();

    const int cbase = warp * 4;
    const int r0 = lane;
    const int r1 = lane + 32;
    const bool has1 = (lane < 10);

    float a0[4] = {0.f, 0.f, 0.f, 0.f};
    float a1[4] = {0.f, 0.f, 0.f, 0.f};

    const float* w0p = ws + r0 * RS_WS;
    const float* w1p = ws + (has1 ? r1 : r0) * RS_WS;

    int i4 = 0;
    for (; i4 + 4 <= IN; i4 += 4) {
        float4 wa = *reinterpret_cast<const float4*>(w0p + i4);
        float4 wb = *reinterpret_cast<const float4*>(w1p + i4);
#pragma unroll
        for (int c = 0; c < 4; ++c) {
            float4 v = *reinterpret_cast<const float4*>(db + (cbase + c) * RS_DS + i4);
            a0[c] = fmaf(wa.x, v.x, a0[c]);
            a0[c] = fmaf(wa.y, v.y, a0[c]);
            a0[c] = fmaf(wa.z, v.z, a0[c]);
            a0[c] = fmaf(wa.w, v.w, a0[c]);
            a1[c] = fmaf(wb.x, v.x, a1[c]);
            a1[c] = fmaf(wb.y, v.y, a1[c]);
            a1[c] = fmaf(wb.z, v.z, a1[c]);
            a1[c] = fmaf(wb.w, v.w, a1[c]);
        }
    }
    for (; i4 < IN; ++i4) {
        float wa = w0p[i4];
        float wb = w1p[i4];
#pragma unroll
        for (int c = 0; c < 4; ++c) {
            float v = db[(cbase + c) * RS_DS + i4];
            a0[c] = fmaf(wa, v, a0[c]);
            a1[c] = fmaf(wb, v, a1[c]);
        }
    }

    const float bia0 = bg[r0];
    const float bia1 = has1 ? bg[r1] : 0.f;
#pragma unroll
    for (int c = 0; c < 4; ++c) {
        db[(cbase + c) * RS_DS + OB + r0] = fmaxf(a0[c] + bia0, 0.f);
        if (has1)
            db[(cbase + c) * RS_DS + OB + r1] = fmaxf(a1[c] + bia1, 0.f);
    }
    __syncthreads();
}

__global__ void __launch_bounds__(160, 1)
k_rest(const float* __restrict__ W2, const float* __restrict__ b2,
       const float* __restrict__ W3, const float* __restrict__ b3,
       const float* __restrict__ W4, const float* __restrict__ b4,
       const float* __restrict__ W5, const float* __restrict__ b5,
       const float* __restrict__ Wlin, const float* __restrict__ blin,
       float* __restrict__ out) {
    extern __shared__ float sm[];
    float* db = sm + RS_SM_D;   // [c 20][chan stride 212]
    float* ws = sm + RS_SM_W;
    float* lg = sm + RS_SM_L;

    const int tid  = threadIdx.x;
    const int lane = tid & 31;
    const int warp = tid >> 5;          // 0..4
    const int b    = blockIdx.x;

    // load c1 (rows 0..41) transposed into db
    for (int idx = tid; idx < OF_ * OS_; idx += 160) {
        int r = idx / OS_;
        int c = idx - r * OS_;
        db[c * RS_DS + r] = g_act[(size_t)r * (B_ * OS_) + b * OS_ + c];
    }
    __syncthreads();

    rest_layer(W2, b2, db, ws,  42,  42, warp, lane, tid);
    rest_layer(W3, b3, db, ws,  84,  84, warp, lane, tid);
    rest_layer(W4, b4, db, ws, 126, 126, warp, lane, tid);
    rest_layer(W5, b5, db, ws, 168, 168, warp, lane, tid);

    // linear head: warp w -> classes 2w, 2w+1. lane<20 handles position c=lane.
    {
        const int n0 = warp * 2;
        const int n1 = n0 + 1;
        float a0 = 0.f, a1 = 0.f;
        if (lane < 20) {
            const float* wl0 = Wlin + (size_t)n0 * (210 * OS_) + lane;
            const float* wl1 = Wlin + (size_t)n1 * (210 * OS_) + lane;
            const float* dp  = db + lane * RS_DS;
#pragma unroll 6
            for (int ch = 0; ch < 210; ++ch) {
                float v = dp[ch];
                a0 = fmaf(wl0[ch * OS_], v, a0);
                a1 = fmaf(wl1[ch * OS_], v, a1);
            }
        }
#pragma unroll
        for (int off = 16; off > 0; off >>= 1) {
            a0 += __shfl_down_sync(0xffffffffu, a0, off);
            a1 += __shfl_down_sync(0xffffffffu, a1, off);
        }
        if (lane == 0) { lg[n0] = a0 + blin[n0]; lg[n1] = a1 + blin[n1]; }
    }
    __syncthreads();

    if (tid == 0) {
        float m = lg[0];
#pragma unroll
        for (int n = 1; n < NC_; ++n) m = fmaxf(m, lg[n]);
        float e[NC_], s = 0.f;
#pragma unroll
        for (int n = 0; n < NC_; ++n) { e[n] = __expf(lg[n] - m); s += e[n]; }
        float invs = 1.f / s;
#pragma unroll
        for (int n = 0; n < NC_; ++n) out[b * NC_ + n] = e[n] * invs;
    }
}

// ============================================================
extern "C" void kernel_launch(void* const* d_in, const int* in_sizes, int n_in,
                              void* d_out, int out_size) {
    const float* y       = (const float*)d_in[0];
    const int*   lengths = (const int*)  d_in[1];
    const float* gamma   = (const float*)d_in[2];
    const float* beta    = (const float*)d_in[3];
    const float* W1 = (const float*)d_in[4];
    const float* b1 = (const float*)d_in[5];
    const float* W2 = (const float*)d_in[6];
    const float* b2 = (const float*)d_in[7];
    const float* W3 = (const float*)d_in[8];
    const float* b3 = (const float*)d_in[9];
    const float* W4 = (const float*)d_in[10];
    const float* b4 = (const float*)d_in[11];
    const float* W5 = (const float*)d_in[12];
    const float* b5 = (const float*)d_in[13];
    const float* Wlin = (const float*)d_in[14];
    const float* blin = (const float*)d_in[15];
    float* out = (float*)d_out;

    const size_t l1_smem = L1_SM_FLOATS * sizeof(float);   // ~155 KB
    const size_t rs_smem = RS_SM_FLOATS * sizeof(float);   // ~46 KB
    cudaFuncSetAttribute(k_l1, cudaFuncAttributeMaxDynamicSharedMemorySize,
                         (int)l1_smem);
    cudaFuncSetAttribute(k_rest, cudaFuncAttributeMaxDynamicSharedMemorySize,
                         (int)rs_smem);

    dim3 g1(NCHUNK_, B_);
    k_pool_partial<<<g1, 128>>>(y, lengths);
    k_pool_finish<<<(B_ * F_) / 256, 256>>>(y, lengths);
    k_bnstats<<<F_, 128>>>(gamma, beta);
    k_l1<<<B_, 256, l1_smem>>>(W1, b1);
    k_rest<<<B_, 160, rs_smem>>>(W2, b2, W3, b3, W4, b4, W5, b5,
                                 Wlin, blin, out);
}

// round 4
// speedup vs baseline: 1.2147x; 1.1076x over previous
#include <cuda_runtime.h>
#include <cuda_bf16.h>
#include <math.h>

// Problem constants
#define B_   128
#define T_   2048
#define F_   512
#define OS_  20
#define OF_  42
#define NC_  10
#define NCHUNK_ 8
#define CHUNK_  256   // NCHUNK_*CHUNK_ == T_
#define NCOL_ (B_ * OS_)   // 2560

// -------- device scratch (no allocation allowed) --------
__device__ float g_partial[B_ * NCHUNK_ * F_];   // 2 MB
__device__ float g_xT[NCOL_ * F_];               // [col=b*20+j][f], 5.24 MB
__device__ float g_act[OF_ * NCOL_];             // c1: [row][col]
__device__ float g_bns[B_ * F_];                 // per-(b,f) sum over 20 j
__device__ float g_bnss[B_ * F_];                // per-(b,f) sumsq
__device__ float g_scale[F_];
__device__ float g_shift[F_];

// ============================================================
// Kernel 1: partial column sums of y over t in [chunk] ∩ [0, fs)
// ============================================================
__global__ void k_pool_partial(const float* __restrict__ y,
                               const int*   __restrict__ lengths) {
    const int c = blockIdx.x;
    const int b = blockIdx.y;
    const int tid = threadIdx.x;

    const int fs = lengths[b] - (OS_ - 1);
    int t0 = c * CHUNK_;
    int t1 = min(t0 + CHUNK_, fs);

    const float4* row = reinterpret_cast<const float4*>(y + (size_t)b * T_ * F_);
    const int rstride = F_ / 4;

    float4 acc = make_float4(0.f, 0.f, 0.f, 0.f);
    int t = t0;
    for (; t + 8 <= t1; t += 8) {
        float4 v0 = __ldcs(&row[(t + 0) * rstride + tid]);
        float4 v1 = __ldcs(&row[(t + 1) * rstride + tid]);
        float4 v2 = __ldcs(&row[(t + 2) * rstride + tid]);
        float4 v3 = __ldcs(&row[(t + 3) * rstride + tid]);
        float4 v4 = __ldcs(&row[(t + 4) * rstride + tid]);
        float4 v5 = __ldcs(&row[(t + 5) * rstride + tid]);
        float4 v6 = __ldcs(&row[(t + 6) * rstride + tid]);
        float4 v7 = __ldcs(&row[(t + 7) * rstride + tid]);
        acc.x += v0.x; acc.y += v0.y; acc.z += v0.z; acc.w += v0.w;
        acc.x += v1.x; acc.y += v1.y; acc.z += v1.z; acc.w += v1.w;
        acc.x += v2.x; acc.y += v2.y; acc.z += v2.z; acc.w += v2.w;
        acc.x += v3.x; acc.y += v3.y; acc.z += v3.z; acc.w += v3.w;
        acc.x += v4.x; acc.y += v4.y; acc.z += v4.z; acc.w += v4.w;
        acc.x += v5.x; acc.y += v5.y; acc.z += v5.z; acc.w += v5.w;
        acc.x += v6.x; acc.y += v6.y; acc.z += v6.z; acc.w += v6.w;
        acc.x += v7.x; acc.y += v7.y; acc.z += v7.z; acc.w += v7.w;
    }
    for (; t < t1; ++t) {
        float4 v = __ldcs(&row[t * rstride + tid]);
        acc.x += v.x; acc.y += v.y; acc.z += v.z; acc.w += v.w;
    }

    float4* out = reinterpret_cast<float4*>(g_partial + (size_t)(b * NCHUNK_ + c) * F_);
    out[tid] = acc;
}

// ============================================================
// Kernel 2: finish pooling + transpose + BN partials.
// block = batch b, 512 threads (thread = f).
// writes g_xT[b*20+j][f] (coalesced via smem transpose),
// g_bns/g_bnss[b][f].
// ============================================================
__global__ void __launch_bounds__(512, 1)
k_pool_finish(const float* __restrict__ y,
              const int*   __restrict__ lengths) {
    __shared__ float sm[F_ * 21];          // [f][j] stride 21 (odd)

    const int b = blockIdx.x;
    const int f = threadIdx.x;

    const int fs = lengths[b] - (OS_ - 1);
    const float inv = 1.0f / (float)fs;

    float base = 0.f;
#pragma unroll
    for (int c = 0; c < NCHUNK_; ++c)
        base += g_partial[(size_t)(b * NCHUNK_ + c) * F_ + f];

    const float* yb = y + (size_t)b * T_ * F_ + f;

    float run = base;
    float s = 0.f, ss = 0.f;
    {
        float v = run * inv;
        sm[f * 21 + 0] = v;
        s += v; ss = fmaf(v, v, ss);
    }
#pragma unroll
    for (int j = 1; j < OS_; ++j) {
        run += yb[(size_t)(fs + j - 1) * F_] - yb[(size_t)(j - 1) * F_];
        float v = run * inv;
        sm[f * 21 + j] = v;
        s += v; ss = fmaf(v, v, ss);
    }
    g_bns [b * F_ + f] = s;
    g_bnss[b * F_ + f] = ss;
    __syncthreads();

    // write transposed rows coalesced: g_xT[(b*20+j)][f]
#pragma unroll
    for (int j = 0; j < OS_; ++j)
        g_xT[(size_t)(b * OS_ + j) * F_ + f] = sm[f * 21 + j];
}

// ============================================================
// Kernel 3: BN stats reduce over b -> fused scale/shift.
// grid = F_ blocks, 128 threads (thread = b).
// ============================================================
__global__ void k_bnstats(const float* __restrict__ gamma,
                          const float* __restrict__ beta) {
    const int f = blockIdx.x;
    const int b = threadIdx.x;

    __shared__ float s1[128];
    __shared__ float s2[128];

    s1[b] = g_bns [b * F_ + f];
    s2[b] = g_bnss[b * F_ + f];
    __syncthreads();
    for (int off = 64; off > 0; off >>= 1) {
        if (b < off) { s1[b] += s1[b + off]; s2[b] += s2[b + off]; }
        __syncthreads();
    }
    if (b == 0) {
        const float n = (float)(B_ * OS_);
        float mu = s1[0] / n;
        float var = s2[0] / n - mu * mu;
        float sc = gamma[f] * rsqrtf(var + 1e-5f);
        g_scale[f] = sc;
        g_shift[f] = beta[f] - mu * sc;
    }
}

// ============================================================
// Kernel 4: layer 1. grid 320 x 128 thr (4 warps).
// warp handles 2 columns; x register-resident (f = lane+32k);
// W1 in smem, read as consecutive-lane LDS.32 (conflict-free).
// ============================================================
__global__ void __launch_bounds__(128, 2)
k_l1(const float* __restrict__ W1, const float* __restrict__ b1) {
    extern __shared__ float ws[];          // [42][512] flat = 21504 floats

    const int tid  = threadIdx.x;
    const int lane = tid & 31;
    const int warp = tid >> 5;             // 0..3

    // stage W1 (flat copy, float4)
    {
        const float4* w4 = reinterpret_cast<const float4*>(W1);
        float4* s4 = reinterpret_cast<float4*>(ws);
        for (int i = tid; i < (OF_ * F_) / 4; i += 128) s4[i] = w4[i];
    }
    __syncthreads();

    const int col0 = (blockIdx.x * 4 + warp) * 2;
    const int col1 = col0 + 1;

    // load + BN-normalize both columns into registers
    float xa[16], xb[16];
    {
        const float* x0 = g_xT + (size_t)col0 * F_;
        const float* x1 = g_xT + (size_t)col1 * F_;
#pragma unroll
        for (int k = 0; k < 16; ++k) {
            int f = lane + 32 * k;
            float sc = g_scale[f];
            float sh = g_shift[f];
            xa[k] = fmaf(x0[f], sc, sh);
            xb[k] = fmaf(x1[f], sc, sh);
        }
    }

    // r-loop: 2 rows per iteration for shfl ILP
#pragma unroll 1
    for (int r = 0; r < OF_; r += 2) {
        const float* wr0 = ws + (r    ) * F_ + lane;
        const float* wr1 = ws + (r + 1) * F_ + lane;
        float a0 = 0.f, a1 = 0.f, a2 = 0.f, a3 = 0.f;
#pragma unroll
        for (int k = 0; k < 16; ++k) {
            float w0 = wr0[32 * k];
            float w1 = wr1[32 * k];
            a0 = fmaf(w0, xa[k], a0);
            a1 = fmaf(w0, xb[k], a1);
            a2 = fmaf(w1, xa[k], a2);
            a3 = fmaf(w1, xb[k], a3);
        }
#pragma unroll
        for (int off = 16; off > 0; off >>= 1) {
            a0 += __shfl_xor_sync(0xffffffffu, a0, off);
            a1 += __shfl_xor_sync(0xffffffffu, a1, off);
            a2 += __shfl_xor_sync(0xffffffffu, a2, off);
            a3 += __shfl_xor_sync(0xffffffffu, a3, off);
        }
        if (lane == 0) {
            float bi0 = b1[r];
            float bi1 = b1[r + 1];
            float2 v0 = make_float2(fmaxf(a0 + bi0, 0.f), fmaxf(a1 + bi0, 0.f));
            float2 v1 = make_float2(fmaxf(a2 + bi1, 0.f), fmaxf(a3 + bi1, 0.f));
            *reinterpret_cast<float2*>(g_act + (size_t)(r    ) * NCOL_ + col0) = v0;
            *reinterpret_cast<float2*>(g_act + (size_t)(r + 1) * NCOL_ + col0) = v1;
        }
    }
}

// ============================================================
// Kernel 5: layers 2..5 + linear head + softmax.
// block = batch, 320 thr (10 warps x 2 private columns).
// All weights pre-staged (zero-padded rows); no inter-layer syncs.
// smem floats: db[20*212] | ws[18144] | lg[16]
// ============================================================
#define DBS 212
#define RS_W   (OS_ * DBS)                  // 4240
#define RS_LG  (RS_W + 18144)               // 22384
#define RS_FLOATS (RS_LG + 16)              // 22400

// weight region offsets / strides / padded-IN
#define W2_OF 0
#define W3_OF 1848
#define W4_OF 5376
#define W5_OF 10920

__device__ __forceinline__ void rest_layer(const float* __restrict__ bg,
                                           float* db, const float* wsl,
                                           int S, int INP, int OB,
                                           int c0, int lane) {
    const int r0 = lane;
    const int r1 = lane + 32;
    const bool has1 = (lane < 10);

    const float* w0 = wsl + r0 * S;
    const float* w1 = wsl + (has1 ? r1 : r0) * S;
    float* d0 = db + (c0    ) * DBS;
    float* d1 = db + (c0 + 1) * DBS;

    float a00 = 0.f, a01 = 0.f, a10 = 0.f, a11 = 0.f;
    for (int i4 = 0; i4 < INP; i4 += 4) {
        float4 wa = *reinterpret_cast<const float4*>(w0 + i4);
        float4 wb = *reinterpret_cast<const float4*>(w1 + i4);
        float4 va = *reinterpret_cast<const float4*>(d0 + i4);
        float4 vb = *reinterpret_cast<const float4*>(d1 + i4);
        a00 = fmaf(wa.x, va.x, a00); a00 = fmaf(wa.y, va.y, a00);
        a00 = fmaf(wa.z, va.z, a00); a00 = fmaf(wa.w, va.w, a00);
        a01 = fmaf(wa.x, vb.x, a01); a01 = fmaf(wa.y, vb.y, a01);
        a01 = fmaf(wa.z, vb.z, a01); a01 = fmaf(wa.w, vb.w, a01);
        a10 = fmaf(wb.x, va.x, a10); a10 = fmaf(wb.y, va.y, a10);
        a10 = fmaf(wb.z, va.z, a10); a10 = fmaf(wb.w, va.w, a10);
        a11 = fmaf(wb.x, vb.x, a11); a11 = fmaf(wb.y, vb.y, a11);
        a11 = fmaf(wb.z, vb.z, a11); a11 = fmaf(wb.w, vb.w, a11);
    }
    float bi0 = bg[r0];
    d0[OB + r0] = fmaxf(a00 + bi0, 0.f);
    d1[OB + r0] = fmaxf(a01 + bi0, 0.f);
    if (has1) {
        float bi1 = bg[r1];
        d0[OB + r1] = fmaxf(a10 + bi1, 0.f);
        d1[OB + r1] = fmaxf(a11 + bi1, 0.f);
    }
    __syncwarp();
}

__global__ void __launch_bounds__(320, 1)
k_rest(const float* __restrict__ W2, const float* __restrict__ b2,
       const float* __restrict__ W3, const float* __restrict__ b3,
       const float* __restrict__ W4, const float* __restrict__ b4,
       const float* __restrict__ W5, const float* __restrict__ b5,
       const float* __restrict__ Wlin, const float* __restrict__ blin,
       float* __restrict__ out) {
    extern __shared__ float sm[];
    float* db = sm;            // [col 20][chan stride 212]
    float* ws = sm + RS_W;
    float* lg = sm + RS_LG;

    const int tid  = threadIdx.x;
    const int lane = tid & 31;
    const int warp = tid >> 5;          // 0..9
    const int b    = blockIdx.x;

    // zero db + ws + lg (padding lanes must be 0)
    for (int i = tid; i < RS_FLOATS; i += 320) sm[i] = 0.f;
    __syncthreads();

    // stage c1 into db (chan 0..41), and all weights (rows padded w/ zeros)
    for (int idx = tid; idx < OF_ * OS_; idx += 320) {
        int chan = idx / OS_;
        int j = idx - chan * OS_;
        db[j * DBS + chan] = g_act[(size_t)chan * NCOL_ + b * OS_ + j];
    }
    for (int idx = tid; idx < OF_ * 42; idx += 320) {
        int o = idx / 42, i = idx - o * 42;
        ws[W2_OF + o * 44 + i] = W2[idx];
    }
    for (int idx = tid; idx < OF_ * 84; idx += 320) {
        int o = idx / 84, i = idx - o * 84;
        ws[W3_OF + o * 84 + i] = W3[idx];
    }
    for (int idx = tid; idx < OF_ * 126; idx += 320) {
        int o = idx / 126, i = idx - o * 126;
        ws[W4_OF + o * 132 + i] = W4[idx];
    }
    for (int idx = tid; idx < OF_ * 168; idx += 320) {
        int o = idx / 168, i = idx - o * 168;
        ws[W5_OF + o * 172 + i] = W5[idx];
    }
    __syncthreads();

    const int c0 = warp * 2;   // this warp's private column pair

    rest_layer(b2, db, ws + W2_OF,  44,  44,  42, c0, lane);
    rest_layer(b3, db, ws + W3_OF,  84,  84,  84, c0, lane);
    rest_layer(b4, db, ws + W4_OF, 132, 128, 126, c0, lane);
    rest_layer(b5, db, ws + W5_OF, 172, 168, 168, c0, lane);

    __syncthreads();

    // linear head: warp n (< 10) computes class n over 4200 flat elems
    if (warp < NC_) {
        const float* wl = Wlin + (size_t)warp * (210 * OS_);
        float acc = 0.f;
        for (int k = lane; k < 210 * OS_; k += 32) {
            int chan = k / OS_;
            int j = k - chan * OS_;
            acc = fmaf(wl[k], db[j * DBS + chan], acc);
        }
#pragma unroll
        for (int off = 16; off > 0; off >>= 1)
            acc += __shfl_xor_sync(0xffffffffu, acc, off);
        if (lane == 0) lg[warp] = acc + blin[warp];
    }
    __syncthreads();

    if (tid == 0) {
        float m = lg[0];
#pragma unroll
        for (int n = 1; n < NC_; ++n) m = fmaxf(m, lg[n]);
        float e[NC_], s = 0.f;
#pragma unroll
        for (int n = 0; n < NC_; ++n) { e[n] = __expf(lg[n] - m); s += e[n]; }
        float invs = 1.f / s;
#pragma unroll
        for (int n = 0; n < NC_; ++n) out[b * NC_ + n] = e[n] * invs;
    }
}

// ============================================================
extern "C" void kernel_launch(void* const* d_in, const int* in_sizes, int n_in,
                              void* d_out, int out_size) {
    const float* y       = (const float*)d_in[0];
    const int*   lengths = (const int*)  d_in[1];
    const float* gamma   = (const float*)d_in[2];
    const float* beta    = (const float*)d_in[3];
    const float* W1 = (const float*)d_in[4];
    const float* b1 = (const float*)d_in[5];
    const float* W2 = (const float*)d_in[6];
    const float* b2 = (const float*)d_in[7];
    const float* W3 = (const float*)d_in[8];
    const float* b3 = (const float*)d_in[9];
    const float* W4 = (const float*)d_in[10];
    const float* b4 = (const float*)d_in[11];
    const float* W5 = (const float*)d_in[12];
    const float* b5 = (const float*)d_in[13];
    const float* Wlin = (const float*)d_in[14];
    const float* blin = (const float*)d_in[15];
    float* out = (float*)d_out;

    const size_t l1_smem = (size_t)OF_ * F_ * sizeof(float);     // 84 KB
    const size_t rs_smem = (size_t)RS_FLOATS * sizeof(float);    // 89.6 KB
    cudaFuncSetAttribute(k_l1, cudaFuncAttributeMaxDynamicSharedMemorySize,
                         (int)l1_smem);
    cudaFuncSetAttribute(k_rest, cudaFuncAttributeMaxDynamicSharedMemorySize,
                         (int)rs_smem);

    dim3 g1(NCHUNK_, B_);
    k_pool_partial<<<g1, 128>>>(y, lengths);
    k_pool_finish<<<B_, 512>>>(y, lengths);
    k_bnstats<<<F_, 128>>>(gamma, beta);
    k_l1<<<320, 128, l1_smem>>>(W1, b1);
    k_rest<<<B_, 320, rs_smem>>>(W2, b2, W3, b3, W4, b4, W5, b5,
                                 Wlin, blin, out);
}